// round 15
// baseline (speedup 1.0000x reference)
#include <cuda_runtime.h>
#include <cuda_bf16.h>
#include <cstdint>
#include <cstddef>

// Problem constants
#define S_TOK 4096      // H*W
#define CDIM  768
#define NH    12
#define QKV_N (3*CDIM)  // 2304
#define NSPLIT 3

// ---------------------------------------------------------------------------
// Scratch (device globals; no dynamic allocation allowed)
// ---------------------------------------------------------------------------
__device__ float g_qkv[(size_t)S_TOK * QKV_N];        // [token][3*768] (tf32-rounded)
__device__ float g_relh[(size_t)NH * 64 * S_TOK];     // [h][kh][q]  (transposed)
__device__ float g_relw[(size_t)NH * S_TOK * 64];     // [h][q][kw]
__device__ float g_attno[(size_t)S_TOK * CDIM];       // [token][h*64+d] (rounded)
__device__ float g_xr[(size_t)S_TOK * CDIM];          // tf32-rounded x
__device__ float g_wr[(size_t)CDIM * QKV_N];          // tf32-rounded weights
__device__ float g_part[(size_t)NSPLIT * NH * S_TOK * 64]; // split partial O
__device__ float g_pml[(size_t)NSPLIT * NH * S_TOK * 2];   // split (m,l) per row

// ---------------------------------------------------------------------------
// Helpers
// ---------------------------------------------------------------------------
__device__ __forceinline__ uint32_t f2tf32(float f) {
    uint32_t u;
    asm("cvt.rna.tf32.f32 %0, %1;" : "=r"(u) : "f"(f));
    return u;
}

__device__ __forceinline__ void mma_tf32(float* c, const uint4& a, const uint2& b) {
    asm volatile(
        "mma.sync.aligned.m16n8k8.row.col.f32.tf32.tf32.f32 "
        "{%0,%1,%2,%3}, {%4,%5,%6,%7}, {%8,%9}, {%0,%1,%2,%3};"
        : "+f"(c[0]), "+f"(c[1]), "+f"(c[2]), "+f"(c[3])
        : "r"(a.x), "r"(a.y), "r"(a.z), "r"(a.w), "r"(b.x), "r"(b.y));
}

__device__ __forceinline__ uint32_t smem_u32(const void* p) {
    uint32_t a;
    asm("{ .reg .u64 t; cvta.to.shared.u64 t, %1; cvt.u32.u64 %0, t; }"
        : "=r"(a) : "l"(p));
    return a;
}

__device__ __forceinline__ void cp16(uint32_t d, const void* s) {
    asm volatile("cp.async.cg.shared.global [%0], [%1], 16;" :: "r"(d), "l"(s));
}
#define CP_COMMIT() asm volatile("cp.async.commit_group;" ::: "memory")
#define CP_WAIT1()  asm volatile("cp.async.wait_group 1;" ::: "memory")
#define CP_WAIT0()  asm volatile("cp.async.wait_group 0;" ::: "memory")

// ---------------------------------------------------------------------------
// tf32 rounding pass (rna) — for GEMM *inputs* only
// ---------------------------------------------------------------------------
__global__ __launch_bounds__(256) void tf32_round_kernel(
    const float* __restrict__ in, float* __restrict__ out, int n4)
{
    int i = blockIdx.x * blockDim.x + threadIdx.x;
    if (i >= n4) return;
    float4 v = ((const float4*)in)[i];
    uint4 u;
    u.x = f2tf32(v.x); u.y = f2tf32(v.y); u.z = f2tf32(v.z); u.w = f2tf32(v.w);
    ((uint4*)out)[i] = u;
}

// ---------------------------------------------------------------------------
// tf32 tensor GEMM + bias, cp.async double-buffered raw tiles, BK=32.
// Inputs A,B must be pre-rounded to tf32. 128x128 tile, 256 threads
// (8 warps: 4 M x 2 N). A tile [128][36], B tile [32][136] (bank-safe:
// A frag bank 4r+c+8ks distinct; B frag bank 8c+r+8nt distinct).
// Same 8-wide k-block visit order as BK=16 -> bit-identical results.
// round_out != 0 -> store tf32-rounded C.
// ---------------------------------------------------------------------------
__global__ __launch_bounds__(256, 2) void gemm_tf32_kernel(
    const float* __restrict__ A, const float* __restrict__ B,
    const float* __restrict__ bias, float* __restrict__ C,
    int M, int N, int K, int round_out)
{
    __shared__ __align__(16) float sA[2][128 * 36];
    __shared__ __align__(16) float sB[2][32 * 136];

    const int tid  = threadIdx.x;
    const int lane = tid & 31;
    const int w    = tid >> 5;
    const int wm   = w & 3;
    const int wn   = w >> 2;
    const int m0   = blockIdx.y * 128;
    const int n0   = blockIdx.x * 128;
    const int nk   = K / 32;

    float Ca[2][8][4];
#pragma unroll
    for (int mb = 0; mb < 2; mb++)
#pragma unroll
        for (int nt = 0; nt < 8; nt++)
#pragma unroll
            for (int j = 0; j < 4; j++) Ca[mb][nt][j] = 0.f;

    // loader mapping (BK=32): A row tid>>1, cols (tid&1)*16 + {0,4,8,12}
    //                         B row tid>>3, cols (tid&7)*16 + {0,4,8,12}
    const int arow = tid >> 1;
    const int ac0  = (tid & 1) * 16;
    const int brow = tid >> 3;
    const int bc0  = (tid & 7) * 16;

    auto issue = [&](int kc, int buf) {
        uint32_t ab = smem_u32(&sA[buf][0]);
        uint32_t bb = smem_u32(&sB[buf][0]);
        int k0 = kc * 32;
        const float* Ap = A + (size_t)(m0 + arow) * K + k0 + ac0;
        const float* Bp = B + (size_t)(k0 + brow) * N + n0 + bc0;
#pragma unroll
        for (int i = 0; i < 4; i++) {
            cp16(ab + (arow * 36 + ac0 + 4 * i) * 4, Ap + 4 * i);
            cp16(bb + (brow * 136 + bc0 + 4 * i) * 4, Bp + 4 * i);
        }
        CP_COMMIT();
    };

    issue(0, 0);

    for (int kc = 0; kc < nk; kc++) {
        const int buf = kc & 1;
        __syncthreads();                       // prev compute done (buffers free)
        if (kc + 1 < nk) { issue(kc + 1, buf ^ 1); CP_WAIT1(); }
        else             { CP_WAIT0(); }
        __syncthreads();                       // tile kc visible

        const uint32_t* ap0 = (const uint32_t*)&sA[buf][0]
                            + (wm * 32 + (lane >> 2)) * 36 + (lane & 3);
        const uint32_t* bp0 = (const uint32_t*)&sB[buf][0]
                            + (lane & 3) * 136 + wn * 64 + (lane >> 2);
#pragma unroll
        for (int ks = 0; ks < 4; ks++) {
            const uint32_t* a = ap0 + ks * 8;
            uint4 A0 = {a[0],       a[8 * 36],       a[4],            a[8 * 36 + 4]};
            uint4 A1 = {a[16 * 36], a[24 * 36],      a[16 * 36 + 4],  a[24 * 36 + 4]};
            const uint32_t* b = bp0 + ks * 8 * 136;
#pragma unroll
            for (int nt = 0; nt < 8; nt++) {
                uint2 bb = {b[nt * 8], b[4 * 136 + nt * 8]};
                mma_tf32(Ca[0][nt], A0, bb);
                mma_tf32(Ca[1][nt], A1, bb);
            }
        }
    }

#pragma unroll
    for (int mb = 0; mb < 2; mb++) {
        int row = m0 + wm * 32 + mb * 16 + (lane >> 2);
#pragma unroll
        for (int nt = 0; nt < 8; nt++) {
            int col = n0 + wn * 64 + nt * 8 + 2 * (lane & 3);
            float bx = bias[col], by = bias[col + 1];
            float e0 = Ca[mb][nt][0] + bx, e1 = Ca[mb][nt][1] + by;
            float e2 = Ca[mb][nt][2] + bx, e3 = Ca[mb][nt][3] + by;
            if (round_out) {
                e0 = __uint_as_float(f2tf32(e0));
                e1 = __uint_as_float(f2tf32(e1));
                e2 = __uint_as_float(f2tf32(e2));
                e3 = __uint_as_float(f2tf32(e3));
            }
            float2 v0 = {e0, e1};
            float2 v1 = {e2, e3};
            *(float2*)(C + (size_t)row * N + col)       = v0;
            *(float2*)(C + (size_t)(row + 8) * N + col) = v1;
        }
    }
}

// ---------------------------------------------------------------------------
// Relative-position tables (exact fp32), both modes in ONE launch (z = mode).
// ---------------------------------------------------------------------------
__global__ __launch_bounds__(256) void relpos_kernel(
    const float* __restrict__ rph, const float* __restrict__ rpw)
{
    __shared__ __align__(16) float Qt[64][68];
    __shared__ __align__(16) float Rt[64][68];

    const int tid  = threadIdx.x;
    const int h    = blockIdx.y;
    const int fixed = blockIdx.x;
    const int mode = blockIdx.z;
    const float* relpos = (mode == 0) ? rph : rpw;

#pragma unroll
    for (int p = 0; p < 4; p++) {
        int f4 = tid + 256 * p;
        int r = f4 >> 4;
        int c4 = (f4 & 15) << 2;
        int token = (mode == 0) ? (fixed * 64 + r) : (r * 64 + fixed);
        *(float4*)&Qt[r][c4] =
            *(const float4*)(g_qkv + (size_t)token * QKV_N + h * 64 + c4);
        int ridx = fixed - r + 63;
        *(float4*)&Rt[r][c4] = *(const float4*)(relpos + ridx * 64 + c4);
    }
    __syncthreads();

    const int tx = tid & 15;
    const int ty = tid >> 4;
    float s[4][4];
#pragma unroll
    for (int i = 0; i < 4; i++)
#pragma unroll
        for (int j = 0; j < 4; j++) s[i][j] = 0.f;

#pragma unroll
    for (int c4 = 0; c4 < 16; c4++) {
        float qr[4][4], kr[4][4];
#pragma unroll
        for (int i = 0; i < 4; i++)
            *(float4*)&qr[i][0] = *(float4*)&Qt[ty + 16 * i][c4 * 4];
#pragma unroll
        for (int j = 0; j < 4; j++)
            *(float4*)&kr[j][0] = *(float4*)&Rt[tx + 16 * j][c4 * 4];
#pragma unroll
        for (int e = 0; e < 4; e++)
#pragma unroll
            for (int i = 0; i < 4; i++)
#pragma unroll
                for (int j = 0; j < 4; j++)
                    s[i][j] += qr[i][e] * kr[j][e];
    }

#pragma unroll
    for (int i = 0; i < 4; i++) {
        int a = ty + 16 * i;
        int token = (mode == 0) ? (fixed * 64 + a) : (a * 64 + fixed);
#pragma unroll
        for (int j = 0; j < 4; j++) {
            int b = tx + 16 * j;
            if (mode == 0)
                g_relh[((size_t)h * 64 + b) * S_TOK + token] = s[i][j];
            else
                g_relw[((size_t)h * S_TOK + token) * 64 + b] = s[i][j];
        }
    }
}

// ---------------------------------------------------------------------------
// Flash attention, 3-way split-KV (unchanged from R14 best).
// ---------------------------------------------------------------------------
#define RWF_OFF  0
#define KV_OFF   32768
#define KVSTRIDE 34816
#define V_SUB    17408
#define FLASH_SMEM 102400

__global__ __launch_bounds__(256, 2) void flash_mma_kernel()
{
    extern __shared__ __align__(16) char smc[];
    float* sRWf = (float*)(smc + RWF_OFF);
    const uint32_t smem_base = smem_u32(smc);

    const int tid  = threadIdx.x;
    const int w    = tid >> 5;
    const int lane = tid & 31;
    const int h    = blockIdx.y;
    const int q0   = blockIdx.x * 128;
    const int sp   = blockIdx.z;
    const int kt0  = (sp == 0) ? 0 : (sp == 1) ? 21 : 42;
    const int kt1  = (sp == 0) ? 21 : (sp == 1) ? 42 : 64;

    // ---- prologue: Q A-frags (raw tf32 bits; 0.125 scale is exact) ----
    const int rq = lane >> 2;
    const int r0 = q0 + w * 16 + rq;
    const int c0 = lane & 3;
    uint4 Qa[8];
    {
        const float* qp0 = g_qkv + (size_t)r0 * QKV_N + h * 64;
        const float* qp8 = qp0 + (size_t)8 * QKV_N;
#pragma unroll
        for (int ks = 0; ks < 8; ks++) {
            Qa[ks].x = __float_as_uint(qp0[ks * 8 + c0]     * 0.125f);
            Qa[ks].y = __float_as_uint(qp8[ks * 8 + c0]     * 0.125f);
            Qa[ks].z = __float_as_uint(qp0[ks * 8 + c0 + 4] * 0.125f);
            Qa[ks].w = __float_as_uint(qp8[ks * 8 + c0 + 4] * 0.125f);
        }
        const float* rw0 = g_relw + ((size_t)h * S_TOK + r0) * 64;
        const float* rw8 = rw0 + 8 * 64;
        const int nb = 2 * (lane & 3);
#pragma unroll
        for (int nt = 0; nt < 8; nt++) {
            float4 v = {rw0[nt * 8 + nb], rw0[nt * 8 + nb + 1],
                        rw8[nt * 8 + nb], rw8[nt * 8 + nb + 1]};
            *(float4*)(sRWf + ((w * 8 + nt) * 32 + lane) * 4) = v;
        }
    }

    float Oa[8][4];
    float m_lo = -1e30f, m_hi = -1e30f, l_lo = 0.f, l_hi = 0.f;
#pragma unroll
    for (int nt = 0; nt < 8; nt++)
#pragma unroll
        for (int j = 0; j < 4; j++) Oa[nt][j] = 0.f;

    const int crow = tid >> 2;
    const int cq16 = (tid & 3) * 16;

    auto issue_kv = [&](int t, int b) {
        const float* kp = g_qkv + (size_t)(t * 64 + crow) * QKV_N + h * 64 + CDIM + cq16;
        uint32_t kd = smem_base + KV_OFF + b * KVSTRIDE + (crow * 68 + cq16) * 4;
        uint32_t vd = smem_base + KV_OFF + b * KVSTRIDE + V_SUB + (crow * 68 + cq16) * 4;
#pragma unroll
        for (int i = 0; i < 4; i++) {
            cp16(kd + i * 16, kp + i * 4);
            cp16(vd + i * 16, kp + CDIM + i * 4);
        }
        CP_COMMIT();
    };

    issue_kv(kt0, 0);

    const float* rh_base = g_relh + (size_t)h * 64 * S_TOK + q0 + w * 16 + rq;

    for (int kt = kt0; kt < kt1; kt++) {
        const int buf = (kt - kt0) & 1;
        __syncthreads();
        if (kt + 1 < kt1) issue_kv(kt + 1, buf ^ 1);
        float rhl = __ldg(rh_base + (size_t)kt * S_TOK);
        float rhh = __ldg(rh_base + (size_t)kt * S_TOK + 8);
        if (kt + 1 < kt1) { CP_WAIT1(); } else { CP_WAIT0(); }
        __syncthreads();

        const uint32_t* kp = (const uint32_t*)(smc + KV_OFF + buf * KVSTRIDE)
                           + (lane >> 2) * 68 + (lane & 3);
        const uint32_t* vp = (const uint32_t*)(smc + KV_OFF + buf * KVSTRIDE + V_SUB)
                           + 2 * (lane & 3) * 68 + (lane >> 2);

        // ---- S = Q @ K^T ----
        float Sa[8][4];
#pragma unroll
        for (int nt = 0; nt < 8; nt++)
#pragma unroll
            for (int j = 0; j < 4; j++) Sa[nt][j] = 0.f;

#pragma unroll
        for (int ks = 0; ks < 8; ks++) {
#pragma unroll
            for (int nt = 0; nt < 8; nt++) {
                uint2 b = {kp[nt * 8 * 68 + ks * 8], kp[nt * 8 * 68 + ks * 8 + 4]};
                mma_tf32(Sa[nt], Qa[ks], b);
            }
        }

        // ---- bias + online softmax (P left in Sa) ----
        float mlo = -1e30f, mhi = -1e30f;
#pragma unroll
        for (int nt = 0; nt < 8; nt++) {
            float4 rw = *(float4*)(sRWf + ((w * 8 + nt) * 32 + lane) * 4);
            Sa[nt][0] += rhl + rw.x;
            Sa[nt][1] += rhl + rw.y;
            Sa[nt][2] += rhh + rw.z;
            Sa[nt][3] += rhh + rw.w;
            mlo = fmaxf(mlo, fmaxf(Sa[nt][0], Sa[nt][1]));
            mhi = fmaxf(mhi, fmaxf(Sa[nt][2], Sa[nt][3]));
        }
        mlo = fmaxf(mlo, __shfl_xor_sync(0xffffffffu, mlo, 1));
        mlo = fmaxf(mlo, __shfl_xor_sync(0xffffffffu, mlo, 2));
        mhi = fmaxf(mhi, __shfl_xor_sync(0xffffffffu, mhi, 1));
        mhi = fmaxf(mhi, __shfl_xor_sync(0xffffffffu, mhi, 2));
        float mnl = fmaxf(m_lo, mlo);
        float mnh = fmaxf(m_hi, mhi);
        float al  = __expf(m_lo - mnl);
        float ah  = __expf(m_hi - mnh);
        m_lo = mnl; m_hi = mnh;

        float rsl = 0.f, rsh = 0.f;
#pragma unroll
        for (int nt = 0; nt < 8; nt++) {
            float p0 = __expf(Sa[nt][0] - mnl);
            float p1 = __expf(Sa[nt][1] - mnl);
            float p2 = __expf(Sa[nt][2] - mnh);
            float p3 = __expf(Sa[nt][3] - mnh);
            rsl += p0 + p1;
            rsh += p2 + p3;
            Sa[nt][0] = p0; Sa[nt][1] = p1; Sa[nt][2] = p2; Sa[nt][3] = p3;
        }
        rsl += __shfl_xor_sync(0xffffffffu, rsl, 1);
        rsl += __shfl_xor_sync(0xffffffffu, rsl, 2);
        rsh += __shfl_xor_sync(0xffffffffu, rsh, 1);
        rsh += __shfl_xor_sync(0xffffffffu, rsh, 2);
        l_lo = l_lo * al + rsl;
        l_hi = l_hi * ah + rsh;

#pragma unroll
        for (int nt = 0; nt < 8; nt++) {
            Oa[nt][0] *= al;
            Oa[nt][1] *= al;
            Oa[nt][2] *= ah;
            Oa[nt][3] *= ah;
        }

        // ---- O += P @ V : P A-frag = permuted C-frag, all in registers ----
#pragma unroll
        for (int ks = 0; ks < 8; ks++) {
            uint4 Pf = {f2tf32(Sa[ks][0]), f2tf32(Sa[ks][2]),
                        f2tf32(Sa[ks][1]), f2tf32(Sa[ks][3])};
            const uint32_t* vk = vp + ks * 8 * 68;
#pragma unroll
            for (int nt = 0; nt < 8; nt++) {
                uint2 b = {vk[nt * 8], vk[68 + nt * 8]};
                mma_tf32(Oa[nt], Pf, b);
            }
        }
    }

    // ---- epilogue: write UNNORMALIZED partial O + (m,l) ----
    float* part = g_part + ((size_t)sp * NH + h) * S_TOK * 64;
#pragma unroll
    for (int nt = 0; nt < 8; nt++) {
        int col = nt * 8 + 2 * (lane & 3);
        float2 v0 = {Oa[nt][0], Oa[nt][1]};
        float2 v1 = {Oa[nt][2], Oa[nt][3]};
        *(float2*)(part + (size_t)r0 * 64 + col)       = v0;
        *(float2*)(part + (size_t)(r0 + 8) * 64 + col) = v1;
    }
    if ((lane & 3) == 0) {
        float* ml = g_pml + ((size_t)sp * NH + h) * S_TOK * 2;
        ml[(size_t)r0 * 2]           = m_lo;
        ml[(size_t)r0 * 2 + 1]       = l_lo;
        ml[(size_t)(r0 + 8) * 2]     = m_hi;
        ml[(size_t)(r0 + 8) * 2 + 1] = l_hi;
    }
}

// ---------------------------------------------------------------------------
// Split-KV merge: one warp per (h, q) row. out[q][h*64+d], tf32-rounded.
// ---------------------------------------------------------------------------
__global__ __launch_bounds__(256) void flash_merge_kernel(float* __restrict__ out)
{
    const int row  = blockIdx.x * 8 + (threadIdx.x >> 5);   // 0..NH*S_TOK-1
    const int lane = threadIdx.x & 31;
    const int h = row >> 12;
    const int q = row & (S_TOK - 1);

    const size_t mlstr = (size_t)NH * S_TOK * 2;
    float m0 = g_pml[(size_t)row * 2],               l0 = g_pml[(size_t)row * 2 + 1];
    float m1 = g_pml[mlstr + (size_t)row * 2],       l1 = g_pml[mlstr + (size_t)row * 2 + 1];
    float m2 = g_pml[2 * mlstr + (size_t)row * 2],   l2 = g_pml[2 * mlstr + (size_t)row * 2 + 1];
    float M  = fmaxf(fmaxf(m0, m1), m2);
    float w0 = __expf(m0 - M), w1 = __expf(m1 - M), w2 = __expf(m2 - M);
    float inv = 1.f / (l0 * w0 + l1 * w1 + l2 * w2);

    const size_t pstr = (size_t)NH * S_TOK * 64;
    const float* p0 = g_part + (size_t)row * 64;
    const float* p1 = p0 + pstr;
    const float* p2 = p1 + pstr;
    float* orow = out + (size_t)q * CDIM + h * 64;
#pragma unroll
    for (int c = 0; c < 2; c++) {
        int d = lane + 32 * c;
        float v = p0[d] * w0 + p1[d] * w1 + p2[d] * w2;
        orow[d] = __uint_as_float(f2tf32(v * inv));
    }
}

// ---------------------------------------------------------------------------
// Launch
// ---------------------------------------------------------------------------
extern "C" void kernel_launch(void* const* d_in, const int* in_sizes, int n_in,
                              void* d_out, int out_size)
{
    const float* x      = (const float*)d_in[0];
    const float* qkv_w  = (const float*)d_in[1];
    const float* qkv_b  = (const float*)d_in[2];
    const float* rph    = (const float*)d_in[3];
    const float* rpw    = (const float*)d_in[4];
    const float* proj_w = (const float*)d_in[5];
    const float* proj_b = (const float*)d_in[6];
    float* out = (float*)d_out;

    float *qkv, *attno, *xr, *wr;
    cudaGetSymbolAddress((void**)&qkv,   g_qkv);
    cudaGetSymbolAddress((void**)&attno, g_attno);
    cudaGetSymbolAddress((void**)&xr,    g_xr);
    cudaGetSymbolAddress((void**)&wr,    g_wr);

    cudaFuncSetAttribute(flash_mma_kernel,
                         cudaFuncAttributeMaxDynamicSharedMemorySize,
                         FLASH_SMEM);

    const int RB = 256;
    // 0. pre-round GEMM inputs to tf32
    {
        int n4 = (S_TOK * CDIM) / 4;
        tf32_round_kernel<<<(n4 + RB - 1) / RB, RB>>>(x, xr, n4);
        n4 = (CDIM * QKV_N) / 4;
        tf32_round_kernel<<<(n4 + RB - 1) / RB, RB>>>(qkv_w, wr, n4);
    }
    // 1. qkv = xr @ wr + qkv_b, output rounded to tf32
    {
        dim3 grid(QKV_N / 128, S_TOK / 128);
        gemm_tf32_kernel<<<grid, 256>>>(xr, wr, qkv_b, qkv,
                                        S_TOK, QKV_N, CDIM, 1);
    }
    // 2. rel-pos tables, both modes in one launch
    {
        dim3 grid(64, NH, 2);
        relpos_kernel<<<grid, 256>>>(rph, rpw);
    }
    // 3. flash attention, 3-way split-KV
    {
        dim3 grid(S_TOK / 128, NH, NSPLIT);
        flash_mma_kernel<<<grid, 256, FLASH_SMEM>>>();
    }
    // 3b. merge splits -> attno (tf32-rounded)
    {
        flash_merge_kernel<<<(NH * S_TOK) / 8, 256>>>(attno);
    }
    // 4. round proj weights, then proj GEMM
    {
        int n4 = (CDIM * CDIM) / 4;
        tf32_round_kernel<<<(n4 + RB - 1) / RB, RB>>>(proj_w, wr, n4);
        dim3 grid(CDIM / 128, S_TOK / 128);
        gemm_tf32_kernel<<<grid, 256>>>(attno, wr, proj_b, out,
                                        S_TOK, CDIM, CDIM, 0);
    }
}

// round 16
// speedup vs baseline: 1.0439x; 1.0439x over previous
#include <cuda_runtime.h>
#include <cuda_bf16.h>
#include <cstdint>
#include <cstddef>

// Problem constants
#define S_TOK 4096      // H*W
#define CDIM  768
#define NH    12
#define QKV_N (3*CDIM)  // 2304
#define NSPLIT 3

// ---------------------------------------------------------------------------
// Scratch (device globals; no dynamic allocation allowed)
// ---------------------------------------------------------------------------
__device__ float g_qkv[(size_t)S_TOK * QKV_N];        // [token][3*768] (tf32-rounded)
__device__ float g_relh[(size_t)NH * 64 * S_TOK];     // [h][kh][q]  (transposed)
__device__ float g_relw[(size_t)NH * S_TOK * 64];     // [h][q][kw]
__device__ float g_attno[(size_t)S_TOK * CDIM];       // [token][h*64+d] (rounded)
__device__ float g_xr[(size_t)S_TOK * CDIM];          // tf32-rounded x
__device__ float g_wr[(size_t)CDIM * QKV_N];          // tf32-rounded weights
__device__ float g_part[(size_t)NSPLIT * NH * S_TOK * 64]; // split partial O
__device__ float g_pml[(size_t)NSPLIT * NH * S_TOK * 2];   // split (m,l) per row

// ---------------------------------------------------------------------------
// Helpers
// ---------------------------------------------------------------------------
__device__ __forceinline__ uint32_t f2tf32(float f) {
    uint32_t u;
    asm("cvt.rna.tf32.f32 %0, %1;" : "=r"(u) : "f"(f));
    return u;
}

__device__ __forceinline__ void mma_tf32(float* c, const uint4& a, const uint2& b) {
    asm volatile(
        "mma.sync.aligned.m16n8k8.row.col.f32.tf32.tf32.f32 "
        "{%0,%1,%2,%3}, {%4,%5,%6,%7}, {%8,%9}, {%0,%1,%2,%3};"
        : "+f"(c[0]), "+f"(c[1]), "+f"(c[2]), "+f"(c[3])
        : "r"(a.x), "r"(a.y), "r"(a.z), "r"(a.w), "r"(b.x), "r"(b.y));
}

__device__ __forceinline__ uint32_t smem_u32(const void* p) {
    uint32_t a;
    asm("{ .reg .u64 t; cvta.to.shared.u64 t, %1; cvt.u32.u64 %0, t; }"
        : "=r"(a) : "l"(p));
    return a;
}

__device__ __forceinline__ void cp16(uint32_t d, const void* s) {
    asm volatile("cp.async.cg.shared.global [%0], [%1], 16;" :: "r"(d), "l"(s));
}
#define CP_COMMIT() asm volatile("cp.async.commit_group;" ::: "memory")
#define CP_WAIT1()  asm volatile("cp.async.wait_group 1;" ::: "memory")
#define CP_WAIT0()  asm volatile("cp.async.wait_group 0;" ::: "memory")

// ---------------------------------------------------------------------------
// tf32 rounding pass (rna) — for GEMM *inputs* only
// ---------------------------------------------------------------------------
__global__ __launch_bounds__(256) void tf32_round_kernel(
    const float* __restrict__ in, float* __restrict__ out, int n4)
{
    int i = blockIdx.x * blockDim.x + threadIdx.x;
    if (i >= n4) return;
    float4 v = ((const float4*)in)[i];
    uint4 u;
    u.x = f2tf32(v.x); u.y = f2tf32(v.y); u.z = f2tf32(v.z); u.w = f2tf32(v.w);
    ((uint4*)out)[i] = u;
}

// ---------------------------------------------------------------------------
// tf32 tensor GEMM + bias. BK=16 tiles/layouts (proven best), upgraded to a
// 3-stage cp.async pipeline: prefetch distance 2, ONE __syncthreads per chunk.
// Invariants: at chunk kc, groups 0..kc+1 issued -> wait<=1 certifies tile kc;
// loop-head sync certifies compute(kc-1) done before buf (kc+2)%3 overwrite.
// A tile [128][20], B tile [16][136] (bank-safe). Results bit-identical.
// round_out != 0 -> store tf32-rounded C.
// ---------------------------------------------------------------------------
__global__ __launch_bounds__(256, 2) void gemm_tf32_kernel(
    const float* __restrict__ A, const float* __restrict__ B,
    const float* __restrict__ bias, float* __restrict__ C,
    int M, int N, int K, int round_out)
{
    __shared__ __align__(16) float sA[3][128 * 20];
    __shared__ __align__(16) float sB[3][16 * 136];

    const int tid  = threadIdx.x;
    const int lane = tid & 31;
    const int w    = tid >> 5;
    const int wm   = w & 3;
    const int wn   = w >> 2;
    const int m0   = blockIdx.y * 128;
    const int n0   = blockIdx.x * 128;
    const int nk   = K / 16;

    float Ca[2][8][4];
#pragma unroll
    for (int mb = 0; mb < 2; mb++)
#pragma unroll
        for (int nt = 0; nt < 8; nt++)
#pragma unroll
            for (int j = 0; j < 4; j++) Ca[mb][nt][j] = 0.f;

    // loader chunk mapping: 2 A-chunks + 2 B-chunks per thread
    const int ac  = tid * 2;
    const int ar0 = ac >> 2, aci0 = (ac & 3) * 4;
    const int ar1 = (ac + 1) >> 2, aci1 = ((ac + 1) & 3) * 4;
    const int bc  = tid * 2;
    const int br0 = bc >> 5, bci0 = (bc & 31) * 4;
    const int br1 = (bc + 1) >> 5, bci1 = ((bc + 1) & 31) * 4;

    auto issue = [&](int kc, int buf) {
        uint32_t ab = smem_u32(&sA[buf][0]);
        uint32_t bb = smem_u32(&sB[buf][0]);
        int k0 = kc * 16;
        cp16(ab + (ar0 * 20 + aci0) * 4, A + (size_t)(m0 + ar0) * K + k0 + aci0);
        cp16(ab + (ar1 * 20 + aci1) * 4, A + (size_t)(m0 + ar1) * K + k0 + aci1);
        cp16(bb + (br0 * 136 + bci0) * 4, B + (size_t)(k0 + br0) * N + n0 + bci0);
        cp16(bb + (br1 * 136 + bci1) * 4, B + (size_t)(k0 + br1) * N + n0 + bci1);
        CP_COMMIT();
    };

    issue(0, 0);
    issue(1, 1);

    int buf = 0;
    for (int kc = 0; kc < nk; kc++) {
        if (kc < nk - 1) { CP_WAIT1(); } else { CP_WAIT0(); }
        __syncthreads();                       // tile kc visible; buf (kc+2)%3 free
        if (kc + 2 < nk) issue(kc + 2, (buf + 2) % 3);

        const uint32_t* ap = (const uint32_t*)&sA[buf][0]
                           + (wm * 32 + (lane >> 2)) * 20 + (lane & 3);
        const uint32_t* bp = (const uint32_t*)&sB[buf][0]
                           + (lane & 3) * 136 + wn * 64 + (lane >> 2);
#pragma unroll
        for (int ks = 0; ks < 2; ks++) {
            const uint32_t* a = ap + ks * 8;
            uint4 A0 = {a[0],        a[8 * 20],        a[4],           a[8 * 20 + 4]};
            uint4 A1 = {a[16 * 20],  a[24 * 20],       a[16 * 20 + 4], a[24 * 20 + 4]};
            const uint32_t* b = bp + ks * 8 * 136;
#pragma unroll
            for (int nt = 0; nt < 8; nt++) {
                uint2 bb = {b[nt * 8], b[4 * 136 + nt * 8]};
                mma_tf32(Ca[0][nt], A0, bb);
                mma_tf32(Ca[1][nt], A1, bb);
            }
        }
        buf = (buf + 1) % 3;
    }

#pragma unroll
    for (int mb = 0; mb < 2; mb++) {
        int row = m0 + wm * 32 + mb * 16 + (lane >> 2);
#pragma unroll
        for (int nt = 0; nt < 8; nt++) {
            int col = n0 + wn * 64 + nt * 8 + 2 * (lane & 3);
            float bx = bias[col], by = bias[col + 1];
            float e0 = Ca[mb][nt][0] + bx, e1 = Ca[mb][nt][1] + by;
            float e2 = Ca[mb][nt][2] + bx, e3 = Ca[mb][nt][3] + by;
            if (round_out) {
                e0 = __uint_as_float(f2tf32(e0));
                e1 = __uint_as_float(f2tf32(e1));
                e2 = __uint_as_float(f2tf32(e2));
                e3 = __uint_as_float(f2tf32(e3));
            }
            float2 v0 = {e0, e1};
            float2 v1 = {e2, e3};
            *(float2*)(C + (size_t)row * N + col)       = v0;
            *(float2*)(C + (size_t)(row + 8) * N + col) = v1;
        }
    }
}

// ---------------------------------------------------------------------------
// Relative-position tables (exact fp32), both modes in ONE launch (z = mode).
// ---------------------------------------------------------------------------
__global__ __launch_bounds__(256) void relpos_kernel(
    const float* __restrict__ rph, const float* __restrict__ rpw)
{
    __shared__ __align__(16) float Qt[64][68];
    __shared__ __align__(16) float Rt[64][68];

    const int tid  = threadIdx.x;
    const int h    = blockIdx.y;
    const int fixed = blockIdx.x;
    const int mode = blockIdx.z;
    const float* relpos = (mode == 0) ? rph : rpw;

#pragma unroll
    for (int p = 0; p < 4; p++) {
        int f4 = tid + 256 * p;
        int r = f4 >> 4;
        int c4 = (f4 & 15) << 2;
        int token = (mode == 0) ? (fixed * 64 + r) : (r * 64 + fixed);
        *(float4*)&Qt[r][c4] =
            *(const float4*)(g_qkv + (size_t)token * QKV_N + h * 64 + c4);
        int ridx = fixed - r + 63;
        *(float4*)&Rt[r][c4] = *(const float4*)(relpos + ridx * 64 + c4);
    }
    __syncthreads();

    const int tx = tid & 15;
    const int ty = tid >> 4;
    float s[4][4];
#pragma unroll
    for (int i = 0; i < 4; i++)
#pragma unroll
        for (int j = 0; j < 4; j++) s[i][j] = 0.f;

#pragma unroll
    for (int c4 = 0; c4 < 16; c4++) {
        float qr[4][4], kr[4][4];
#pragma unroll
        for (int i = 0; i < 4; i++)
            *(float4*)&qr[i][0] = *(float4*)&Qt[ty + 16 * i][c4 * 4];
#pragma unroll
        for (int j = 0; j < 4; j++)
            *(float4*)&kr[j][0] = *(float4*)&Rt[tx + 16 * j][c4 * 4];
#pragma unroll
        for (int e = 0; e < 4; e++)
#pragma unroll
            for (int i = 0; i < 4; i++)
#pragma unroll
                for (int j = 0; j < 4; j++)
                    s[i][j] += qr[i][e] * kr[j][e];
    }

#pragma unroll
    for (int i = 0; i < 4; i++) {
        int a = ty + 16 * i;
        int token = (mode == 0) ? (fixed * 64 + a) : (a * 64 + fixed);
#pragma unroll
        for (int j = 0; j < 4; j++) {
            int b = tx + 16 * j;
            if (mode == 0)
                g_relh[((size_t)h * 64 + b) * S_TOK + token] = s[i][j];
            else
                g_relw[((size_t)h * S_TOK + token) * 64 + b] = s[i][j];
        }
    }
}

// ---------------------------------------------------------------------------
// Flash attention, 3-way split-KV (unchanged from R14 best).
// ---------------------------------------------------------------------------
#define RWF_OFF  0
#define KV_OFF   32768
#define KVSTRIDE 34816
#define V_SUB    17408
#define FLASH_SMEM 102400

__global__ __launch_bounds__(256, 2) void flash_mma_kernel()
{
    extern __shared__ __align__(16) char smc[];
    float* sRWf = (float*)(smc + RWF_OFF);
    const uint32_t smem_base = smem_u32(smc);

    const int tid  = threadIdx.x;
    const int w    = tid >> 5;
    const int lane = tid & 31;
    const int h    = blockIdx.y;
    const int q0   = blockIdx.x * 128;
    const int sp   = blockIdx.z;
    const int kt0  = (sp == 0) ? 0 : (sp == 1) ? 21 : 42;
    const int kt1  = (sp == 0) ? 21 : (sp == 1) ? 42 : 64;

    // ---- prologue: Q A-frags (raw tf32 bits; 0.125 scale is exact) ----
    const int rq = lane >> 2;
    const int r0 = q0 + w * 16 + rq;
    const int c0 = lane & 3;
    uint4 Qa[8];
    {
        const float* qp0 = g_qkv + (size_t)r0 * QKV_N + h * 64;
        const float* qp8 = qp0 + (size_t)8 * QKV_N;
#pragma unroll
        for (int ks = 0; ks < 8; ks++) {
            Qa[ks].x = __float_as_uint(qp0[ks * 8 + c0]     * 0.125f);
            Qa[ks].y = __float_as_uint(qp8[ks * 8 + c0]     * 0.125f);
            Qa[ks].z = __float_as_uint(qp0[ks * 8 + c0 + 4] * 0.125f);
            Qa[ks].w = __float_as_uint(qp8[ks * 8 + c0 + 4] * 0.125f);
        }
        const float* rw0 = g_relw + ((size_t)h * S_TOK + r0) * 64;
        const float* rw8 = rw0 + 8 * 64;
        const int nb = 2 * (lane & 3);
#pragma unroll
        for (int nt = 0; nt < 8; nt++) {
            float4 v = {rw0[nt * 8 + nb], rw0[nt * 8 + nb + 1],
                        rw8[nt * 8 + nb], rw8[nt * 8 + nb + 1]};
            *(float4*)(sRWf + ((w * 8 + nt) * 32 + lane) * 4) = v;
        }
    }

    float Oa[8][4];
    float m_lo = -1e30f, m_hi = -1e30f, l_lo = 0.f, l_hi = 0.f;
#pragma unroll
    for (int nt = 0; nt < 8; nt++)
#pragma unroll
        for (int j = 0; j < 4; j++) Oa[nt][j] = 0.f;

    const int crow = tid >> 2;
    const int cq16 = (tid & 3) * 16;

    auto issue_kv = [&](int t, int b) {
        const float* kp = g_qkv + (size_t)(t * 64 + crow) * QKV_N + h * 64 + CDIM + cq16;
        uint32_t kd = smem_base + KV_OFF + b * KVSTRIDE + (crow * 68 + cq16) * 4;
        uint32_t vd = smem_base + KV_OFF + b * KVSTRIDE + V_SUB + (crow * 68 + cq16) * 4;
#pragma unroll
        for (int i = 0; i < 4; i++) {
            cp16(kd + i * 16, kp + i * 4);
            cp16(vd + i * 16, kp + CDIM + i * 4);
        }
        CP_COMMIT();
    };

    issue_kv(kt0, 0);

    const float* rh_base = g_relh + (size_t)h * 64 * S_TOK + q0 + w * 16 + rq;

    for (int kt = kt0; kt < kt1; kt++) {
        const int buf = (kt - kt0) & 1;
        __syncthreads();
        if (kt + 1 < kt1) issue_kv(kt + 1, buf ^ 1);
        float rhl = __ldg(rh_base + (size_t)kt * S_TOK);
        float rhh = __ldg(rh_base + (size_t)kt * S_TOK + 8);
        if (kt + 1 < kt1) { CP_WAIT1(); } else { CP_WAIT0(); }
        __syncthreads();

        const uint32_t* kp = (const uint32_t*)(smc + KV_OFF + buf * KVSTRIDE)
                           + (lane >> 2) * 68 + (lane & 3);
        const uint32_t* vp = (const uint32_t*)(smc + KV_OFF + buf * KVSTRIDE + V_SUB)
                           + 2 * (lane & 3) * 68 + (lane >> 2);

        // ---- S = Q @ K^T ----
        float Sa[8][4];
#pragma unroll
        for (int nt = 0; nt < 8; nt++)
#pragma unroll
            for (int j = 0; j < 4; j++) Sa[nt][j] = 0.f;

#pragma unroll
        for (int ks = 0; ks < 8; ks++) {
#pragma unroll
            for (int nt = 0; nt < 8; nt++) {
                uint2 b = {kp[nt * 8 * 68 + ks * 8], kp[nt * 8 * 68 + ks * 8 + 4]};
                mma_tf32(Sa[nt], Qa[ks], b);
            }
        }

        // ---- bias + online softmax (P left in Sa) ----
        float mlo = -1e30f, mhi = -1e30f;
#pragma unroll
        for (int nt = 0; nt < 8; nt++) {
            float4 rw = *(float4*)(sRWf + ((w * 8 + nt) * 32 + lane) * 4);
            Sa[nt][0] += rhl + rw.x;
            Sa[nt][1] += rhl + rw.y;
            Sa[nt][2] += rhh + rw.z;
            Sa[nt][3] += rhh + rw.w;
            mlo = fmaxf(mlo, fmaxf(Sa[nt][0], Sa[nt][1]));
            mhi = fmaxf(mhi, fmaxf(Sa[nt][2], Sa[nt][3]));
        }
        mlo = fmaxf(mlo, __shfl_xor_sync(0xffffffffu, mlo, 1));
        mlo = fmaxf(mlo, __shfl_xor_sync(0xffffffffu, mlo, 2));
        mhi = fmaxf(mhi, __shfl_xor_sync(0xffffffffu, mhi, 1));
        mhi = fmaxf(mhi, __shfl_xor_sync(0xffffffffu, mhi, 2));
        float mnl = fmaxf(m_lo, mlo);
        float mnh = fmaxf(m_hi, mhi);
        float al  = __expf(m_lo - mnl);
        float ah  = __expf(m_hi - mnh);
        m_lo = mnl; m_hi = mnh;

        float rsl = 0.f, rsh = 0.f;
#pragma unroll
        for (int nt = 0; nt < 8; nt++) {
            float p0 = __expf(Sa[nt][0] - mnl);
            float p1 = __expf(Sa[nt][1] - mnl);
            float p2 = __expf(Sa[nt][2] - mnh);
            float p3 = __expf(Sa[nt][3] - mnh);
            rsl += p0 + p1;
            rsh += p2 + p3;
            Sa[nt][0] = p0; Sa[nt][1] = p1; Sa[nt][2] = p2; Sa[nt][3] = p3;
        }
        rsl += __shfl_xor_sync(0xffffffffu, rsl, 1);
        rsl += __shfl_xor_sync(0xffffffffu, rsl, 2);
        rsh += __shfl_xor_sync(0xffffffffu, rsh, 1);
        rsh += __shfl_xor_sync(0xffffffffu, rsh, 2);
        l_lo = l_lo * al + rsl;
        l_hi = l_hi * ah + rsh;

#pragma unroll
        for (int nt = 0; nt < 8; nt++) {
            Oa[nt][0] *= al;
            Oa[nt][1] *= al;
            Oa[nt][2] *= ah;
            Oa[nt][3] *= ah;
        }

        // ---- O += P @ V : P A-frag = permuted C-frag, all in registers ----
#pragma unroll
        for (int ks = 0; ks < 8; ks++) {
            uint4 Pf = {f2tf32(Sa[ks][0]), f2tf32(Sa[ks][2]),
                        f2tf32(Sa[ks][1]), f2tf32(Sa[ks][3])};
            const uint32_t* vk = vp + ks * 8 * 68;
#pragma unroll
            for (int nt = 0; nt < 8; nt++) {
                uint2 b = {vk[nt * 8], vk[68 + nt * 8]};
                mma_tf32(Oa[nt], Pf, b);
            }
        }
    }

    // ---- epilogue: write UNNORMALIZED partial O + (m,l) ----
    float* part = g_part + ((size_t)sp * NH + h) * S_TOK * 64;
#pragma unroll
    for (int nt = 0; nt < 8; nt++) {
        int col = nt * 8 + 2 * (lane & 3);
        float2 v0 = {Oa[nt][0], Oa[nt][1]};
        float2 v1 = {Oa[nt][2], Oa[nt][3]};
        *(float2*)(part + (size_t)r0 * 64 + col)       = v0;
        *(float2*)(part + (size_t)(r0 + 8) * 64 + col) = v1;
    }
    if ((lane & 3) == 0) {
        float* ml = g_pml + ((size_t)sp * NH + h) * S_TOK * 2;
        ml[(size_t)r0 * 2]           = m_lo;
        ml[(size_t)r0 * 2 + 1]       = l_lo;
        ml[(size_t)(r0 + 8) * 2]     = m_hi;
        ml[(size_t)(r0 + 8) * 2 + 1] = l_hi;
    }
}

// ---------------------------------------------------------------------------
// Split-KV merge: one warp per (h, q) row. out[q][h*64+d], tf32-rounded.
// ---------------------------------------------------------------------------
__global__ __launch_bounds__(256) void flash_merge_kernel(float* __restrict__ out)
{
    const int row  = blockIdx.x * 8 + (threadIdx.x >> 5);   // 0..NH*S_TOK-1
    const int lane = threadIdx.x & 31;
    const int h = row >> 12;
    const int q = row & (S_TOK - 1);

    const size_t mlstr = (size_t)NH * S_TOK * 2;
    float m0 = g_pml[(size_t)row * 2],               l0 = g_pml[(size_t)row * 2 + 1];
    float m1 = g_pml[mlstr + (size_t)row * 2],       l1 = g_pml[mlstr + (size_t)row * 2 + 1];
    float m2 = g_pml[2 * mlstr + (size_t)row * 2],   l2 = g_pml[2 * mlstr + (size_t)row * 2 + 1];
    float M  = fmaxf(fmaxf(m0, m1), m2);
    float w0 = __expf(m0 - M), w1 = __expf(m1 - M), w2 = __expf(m2 - M);
    float inv = 1.f / (l0 * w0 + l1 * w1 + l2 * w2);

    const size_t pstr = (size_t)NH * S_TOK * 64;
    const float* p0 = g_part + (size_t)row * 64;
    const float* p1 = p0 + pstr;
    const float* p2 = p1 + pstr;
    float* orow = out + (size_t)q * CDIM + h * 64;
#pragma unroll
    for (int c = 0; c < 2; c++) {
        int d = lane + 32 * c;
        float v = p0[d] * w0 + p1[d] * w1 + p2[d] * w2;
        orow[d] = __uint_as_float(f2tf32(v * inv));
    }
}

// ---------------------------------------------------------------------------
// Launch
// ---------------------------------------------------------------------------
extern "C" void kernel_launch(void* const* d_in, const int* in_sizes, int n_in,
                              void* d_out, int out_size)
{
    const float* x      = (const float*)d_in[0];
    const float* qkv_w  = (const float*)d_in[1];
    const float* qkv_b  = (const float*)d_in[2];
    const float* rph    = (const float*)d_in[3];
    const float* rpw    = (const float*)d_in[4];
    const float* proj_w = (const float*)d_in[5];
    const float* proj_b = (const float*)d_in[6];
    float* out = (float*)d_out;

    float *qkv, *attno, *xr, *wr;
    cudaGetSymbolAddress((void**)&qkv,   g_qkv);
    cudaGetSymbolAddress((void**)&attno, g_attno);
    cudaGetSymbolAddress((void**)&xr,    g_xr);
    cudaGetSymbolAddress((void**)&wr,    g_wr);

    cudaFuncSetAttribute(flash_mma_kernel,
                         cudaFuncAttributeMaxDynamicSharedMemorySize,
                         FLASH_SMEM);

    const int RB = 256;
    // 0. pre-round GEMM inputs to tf32
    {
        int n4 = (S_TOK * CDIM) / 4;
        tf32_round_kernel<<<(n4 + RB - 1) / RB, RB>>>(x, xr, n4);
        n4 = (CDIM * QKV_N) / 4;
        tf32_round_kernel<<<(n4 + RB - 1) / RB, RB>>>(qkv_w, wr, n4);
    }
    // 1. qkv = xr @ wr + qkv_b, output rounded to tf32
    {
        dim3 grid(QKV_N / 128, S_TOK / 128);
        gemm_tf32_kernel<<<grid, 256>>>(xr, wr, qkv_b, qkv,
                                        S_TOK, QKV_N, CDIM, 1);
    }
    // 2. rel-pos tables, both modes in one launch
    {
        dim3 grid(64, NH, 2);
        relpos_kernel<<<grid, 256>>>(rph, rpw);
    }
    // 3. flash attention, 3-way split-KV
    {
        dim3 grid(S_TOK / 128, NH, NSPLIT);
        flash_mma_kernel<<<grid, 256, FLASH_SMEM>>>();
    }
    // 3b. merge splits -> attno (tf32-rounded)
    {
        flash_merge_kernel<<<(NH * S_TOK) / 8, 256>>>(attno);
    }
    // 4. round proj weights, then proj GEMM
    {
        int n4 = (CDIM * CDIM) / 4;
        tf32_round_kernel<<<(n4 + RB - 1) / RB, RB>>>(proj_w, wr, n4);
        dim3 grid(CDIM / 128, S_TOK / 128);
        gemm_tf32_kernel<<<grid, 256>>>(attno, wr, proj_b, out,
                                        S_TOK, CDIM, CDIM, 0);
    }
}

// round 17
// speedup vs baseline: 1.0572x; 1.0127x over previous
#include <cuda_runtime.h>
#include <cuda_bf16.h>
#include <cstdint>
#include <cstddef>

// Problem constants
#define S_TOK 4096      // H*W
#define CDIM  768
#define NH    12
#define QKV_N (3*CDIM)  // 2304
#define NSPLIT 3
#define LOG2E 1.4426950408889634f

// ---------------------------------------------------------------------------
// Scratch (device globals; no dynamic allocation allowed)
// ---------------------------------------------------------------------------
__device__ float g_qkv[(size_t)S_TOK * QKV_N];        // [token][3*768] (tf32-rounded)
__device__ float g_relh[(size_t)NH * 64 * S_TOK];     // [h][kh][q] (x log2e)
__device__ float g_relw[(size_t)NH * S_TOK * 64];     // [h][q][kw] (x log2e)
__device__ float g_attno[(size_t)S_TOK * CDIM];       // [token][h*64+d] (rounded)
__device__ float g_xr[(size_t)S_TOK * CDIM];          // tf32-rounded x
__device__ float g_wr[(size_t)CDIM * QKV_N];          // tf32-rounded weights
__device__ float g_part[(size_t)NSPLIT * NH * S_TOK * 64]; // split partial O
__device__ float g_pml[(size_t)NSPLIT * NH * S_TOK * 2];   // split (m,l), m in log2

// ---------------------------------------------------------------------------
// Helpers
// ---------------------------------------------------------------------------
__device__ __forceinline__ uint32_t f2tf32(float f) {
    uint32_t u;
    asm("cvt.rna.tf32.f32 %0, %1;" : "=r"(u) : "f"(f));
    return u;
}

__device__ __forceinline__ float ex2(float x) {
    float r;
    asm("ex2.approx.f32 %0, %1;" : "=f"(r) : "f"(x));
    return r;
}

__device__ __forceinline__ void mma_tf32(float* c, const uint4& a, const uint2& b) {
    asm volatile(
        "mma.sync.aligned.m16n8k8.row.col.f32.tf32.tf32.f32 "
        "{%0,%1,%2,%3}, {%4,%5,%6,%7}, {%8,%9}, {%0,%1,%2,%3};"
        : "+f"(c[0]), "+f"(c[1]), "+f"(c[2]), "+f"(c[3])
        : "r"(a.x), "r"(a.y), "r"(a.z), "r"(a.w), "r"(b.x), "r"(b.y));
}

__device__ __forceinline__ uint32_t smem_u32(const void* p) {
    uint32_t a;
    asm("{ .reg .u64 t; cvta.to.shared.u64 t, %1; cvt.u32.u64 %0, t; }"
        : "=r"(a) : "l"(p));
    return a;
}

__device__ __forceinline__ void cp16(uint32_t d, const void* s) {
    asm volatile("cp.async.cg.shared.global [%0], [%1], 16;" :: "r"(d), "l"(s));
}
#define CP_COMMIT() asm volatile("cp.async.commit_group;" ::: "memory")
#define CP_WAIT1()  asm volatile("cp.async.wait_group 1;" ::: "memory")
#define CP_WAIT0()  asm volatile("cp.async.wait_group 0;" ::: "memory")

// ---------------------------------------------------------------------------
// Fused tf32 rounding pass for BOTH GEMM inputs (x and qkv_w) in one launch
// ---------------------------------------------------------------------------
__global__ __launch_bounds__(256) void tf32_round2_kernel(
    const float* __restrict__ inA, float* __restrict__ outA, int n4A,
    const float* __restrict__ inB, float* __restrict__ outB, int n4B)
{
    int i = blockIdx.x * blockDim.x + threadIdx.x;
    const float* in;
    float* out;
    if (i < n4A) { in = inA; out = outA; }
    else if (i < n4A + n4B) { in = inB; out = outB; i -= n4A; }
    else return;
    float4 v = ((const float4*)in)[i];
    uint4 u;
    u.x = f2tf32(v.x); u.y = f2tf32(v.y); u.z = f2tf32(v.z); u.w = f2tf32(v.w);
    ((uint4*)out)[i] = u;
}

__global__ __launch_bounds__(256) void tf32_round_kernel(
    const float* __restrict__ in, float* __restrict__ out, int n4)
{
    int i = blockIdx.x * blockDim.x + threadIdx.x;
    if (i >= n4) return;
    float4 v = ((const float4*)in)[i];
    uint4 u;
    u.x = f2tf32(v.x); u.y = f2tf32(v.y); u.z = f2tf32(v.z); u.w = f2tf32(v.w);
    ((uint4*)out)[i] = u;
}

// ---------------------------------------------------------------------------
// tf32 tensor GEMM + bias, cp.async double-buffered raw tiles (BK=16, R14 form).
// ---------------------------------------------------------------------------
__global__ __launch_bounds__(256, 2) void gemm_tf32_kernel(
    const float* __restrict__ A, const float* __restrict__ B,
    const float* __restrict__ bias, float* __restrict__ C,
    int M, int N, int K, int round_out)
{
    __shared__ __align__(16) float sA[2][128 * 20];
    __shared__ __align__(16) float sB[2][16 * 136];

    const int tid  = threadIdx.x;
    const int lane = tid & 31;
    const int w    = tid >> 5;
    const int wm   = w & 3;
    const int wn   = w >> 2;
    const int m0   = blockIdx.y * 128;
    const int n0   = blockIdx.x * 128;
    const int nk   = K / 16;

    float Ca[2][8][4];
#pragma unroll
    for (int mb = 0; mb < 2; mb++)
#pragma unroll
        for (int nt = 0; nt < 8; nt++)
#pragma unroll
            for (int j = 0; j < 4; j++) Ca[mb][nt][j] = 0.f;

    const int ac  = tid * 2;
    const int ar0 = ac >> 2, aci0 = (ac & 3) * 4;
    const int ar1 = (ac + 1) >> 2, aci1 = ((ac + 1) & 3) * 4;
    const int bc  = tid * 2;
    const int br0 = bc >> 5, bci0 = (bc & 31) * 4;
    const int br1 = (bc + 1) >> 5, bci1 = ((bc + 1) & 31) * 4;

    auto issue = [&](int kc, int buf) {
        uint32_t ab = smem_u32(&sA[buf][0]);
        uint32_t bb = smem_u32(&sB[buf][0]);
        int k0 = kc * 16;
        cp16(ab + (ar0 * 20 + aci0) * 4, A + (size_t)(m0 + ar0) * K + k0 + aci0);
        cp16(ab + (ar1 * 20 + aci1) * 4, A + (size_t)(m0 + ar1) * K + k0 + aci1);
        cp16(bb + (br0 * 136 + bci0) * 4, B + (size_t)(k0 + br0) * N + n0 + bci0);
        cp16(bb + (br1 * 136 + bci1) * 4, B + (size_t)(k0 + br1) * N + n0 + bci1);
        CP_COMMIT();
    };

    issue(0, 0);

    for (int kc = 0; kc < nk; kc++) {
        const int buf = kc & 1;
        __syncthreads();
        if (kc + 1 < nk) { issue(kc + 1, buf ^ 1); CP_WAIT1(); }
        else             { CP_WAIT0(); }
        __syncthreads();

        const uint32_t* ap = (const uint32_t*)&sA[buf][0]
                           + (wm * 32 + (lane >> 2)) * 20 + (lane & 3);
        const uint32_t* bp = (const uint32_t*)&sB[buf][0]
                           + (lane & 3) * 136 + wn * 64 + (lane >> 2);
#pragma unroll
        for (int ks = 0; ks < 2; ks++) {
            const uint32_t* a = ap + ks * 8;
            uint4 A0 = {a[0],        a[8 * 20],        a[4],           a[8 * 20 + 4]};
            uint4 A1 = {a[16 * 20],  a[24 * 20],       a[16 * 20 + 4], a[24 * 20 + 4]};
            const uint32_t* b = bp + ks * 8 * 136;
#pragma unroll
            for (int nt = 0; nt < 8; nt++) {
                uint2 bb = {b[nt * 8], b[4 * 136 + nt * 8]};
                mma_tf32(Ca[0][nt], A0, bb);
                mma_tf32(Ca[1][nt], A1, bb);
            }
        }
    }

#pragma unroll
    for (int mb = 0; mb < 2; mb++) {
        int row = m0 + wm * 32 + mb * 16 + (lane >> 2);
#pragma unroll
        for (int nt = 0; nt < 8; nt++) {
            int col = n0 + wn * 64 + nt * 8 + 2 * (lane & 3);
            float bx = bias[col], by = bias[col + 1];
            float e0 = Ca[mb][nt][0] + bx, e1 = Ca[mb][nt][1] + by;
            float e2 = Ca[mb][nt][2] + bx, e3 = Ca[mb][nt][3] + by;
            if (round_out) {
                e0 = __uint_as_float(f2tf32(e0));
                e1 = __uint_as_float(f2tf32(e1));
                e2 = __uint_as_float(f2tf32(e2));
                e3 = __uint_as_float(f2tf32(e3));
            }
            float2 v0 = {e0, e1};
            float2 v1 = {e2, e3};
            *(float2*)(C + (size_t)row * N + col)       = v0;
            *(float2*)(C + (size_t)(row + 8) * N + col) = v1;
        }
    }
}

// ---------------------------------------------------------------------------
// Relative-position tables (exact fp32 math), both modes in ONE launch.
// Output pre-scaled by log2e (softmax runs in base-2 downstream).
// ---------------------------------------------------------------------------
__global__ __launch_bounds__(256) void relpos_kernel(
    const float* __restrict__ rph, const float* __restrict__ rpw)
{
    __shared__ __align__(16) float Qt[64][68];
    __shared__ __align__(16) float Rt[64][68];

    const int tid  = threadIdx.x;
    const int h    = blockIdx.y;
    const int fixed = blockIdx.x;
    const int mode = blockIdx.z;
    const float* relpos = (mode == 0) ? rph : rpw;

#pragma unroll
    for (int p = 0; p < 4; p++) {
        int f4 = tid + 256 * p;
        int r = f4 >> 4;
        int c4 = (f4 & 15) << 2;
        int token = (mode == 0) ? (fixed * 64 + r) : (r * 64 + fixed);
        *(float4*)&Qt[r][c4] =
            *(const float4*)(g_qkv + (size_t)token * QKV_N + h * 64 + c4);
        int ridx = fixed - r + 63;
        *(float4*)&Rt[r][c4] = *(const float4*)(relpos + ridx * 64 + c4);
    }
    __syncthreads();

    const int tx = tid & 15;
    const int ty = tid >> 4;
    float s[4][4];
#pragma unroll
    for (int i = 0; i < 4; i++)
#pragma unroll
        for (int j = 0; j < 4; j++) s[i][j] = 0.f;

#pragma unroll
    for (int c4 = 0; c4 < 16; c4++) {
        float qr[4][4], kr[4][4];
#pragma unroll
        for (int i = 0; i < 4; i++)
            *(float4*)&qr[i][0] = *(float4*)&Qt[ty + 16 * i][c4 * 4];
#pragma unroll
        for (int j = 0; j < 4; j++)
            *(float4*)&kr[j][0] = *(float4*)&Rt[tx + 16 * j][c4 * 4];
#pragma unroll
        for (int e = 0; e < 4; e++)
#pragma unroll
            for (int i = 0; i < 4; i++)
#pragma unroll
                for (int j = 0; j < 4; j++)
                    s[i][j] += qr[i][e] * kr[j][e];
    }

#pragma unroll
    for (int i = 0; i < 4; i++) {
        int a = ty + 16 * i;
        int token = (mode == 0) ? (fixed * 64 + a) : (a * 64 + fixed);
#pragma unroll
        for (int j = 0; j < 4; j++) {
            int b = tx + 16 * j;
            float v = s[i][j] * LOG2E;
            if (mode == 0)
                g_relh[((size_t)h * 64 + b) * S_TOK + token] = v;
            else
                g_relw[((size_t)h * S_TOK + token) * 64 + b] = v;
        }
    }
}

// ---------------------------------------------------------------------------
// Flash attention, 3-way split-KV, base-2 softmax (ex2.approx).
// Q pre-scaled by 0.125*log2e then rna-rounded to tf32 (exact MMA operand).
// rel tables already carry the log2e factor. Structure identical to R14 best.
// ---------------------------------------------------------------------------
#define RWF_OFF  0
#define KV_OFF   32768
#define KVSTRIDE 34816
#define V_SUB    17408
#define FLASH_SMEM 102400

__global__ __launch_bounds__(256, 2) void flash_mma_kernel()
{
    extern __shared__ __align__(16) char smc[];
    float* sRWf = (float*)(smc + RWF_OFF);
    const uint32_t smem_base = smem_u32(smc);

    const int tid  = threadIdx.x;
    const int w    = tid >> 5;
    const int lane = tid & 31;
    const int h    = blockIdx.y;
    const int q0   = blockIdx.x * 128;
    const int sp   = blockIdx.z;
    const int kt0  = (sp == 0) ? 0 : (sp == 1) ? 21 : 42;
    const int kt1  = (sp == 0) ? 21 : (sp == 1) ? 42 : 64;

    // ---- prologue: Q A-frags scaled by 0.125*log2e, rna-rounded ----
    const int rq = lane >> 2;
    const int r0 = q0 + w * 16 + rq;
    const int c0 = lane & 3;
    const float SCL = 0.125f * LOG2E;
    uint4 Qa[8];
    {
        const float* qp0 = g_qkv + (size_t)r0 * QKV_N + h * 64;
        const float* qp8 = qp0 + (size_t)8 * QKV_N;
#pragma unroll
        for (int ks = 0; ks < 8; ks++) {
            Qa[ks].x = f2tf32(qp0[ks * 8 + c0]     * SCL);
            Qa[ks].y = f2tf32(qp8[ks * 8 + c0]     * SCL);
            Qa[ks].z = f2tf32(qp0[ks * 8 + c0 + 4] * SCL);
            Qa[ks].w = f2tf32(qp8[ks * 8 + c0 + 4] * SCL);
        }
        const float* rw0 = g_relw + ((size_t)h * S_TOK + r0) * 64;
        const float* rw8 = rw0 + 8 * 64;
        const int nb = 2 * (lane & 3);
#pragma unroll
        for (int nt = 0; nt < 8; nt++) {
            float4 v = {rw0[nt * 8 + nb], rw0[nt * 8 + nb + 1],
                        rw8[nt * 8 + nb], rw8[nt * 8 + nb + 1]};
            *(float4*)(sRWf + ((w * 8 + nt) * 32 + lane) * 4) = v;
        }
    }

    float Oa[8][4];
    float m_lo = -1e30f, m_hi = -1e30f, l_lo = 0.f, l_hi = 0.f;
#pragma unroll
    for (int nt = 0; nt < 8; nt++)
#pragma unroll
        for (int j = 0; j < 4; j++) Oa[nt][j] = 0.f;

    const int crow = tid >> 2;
    const int cq16 = (tid & 3) * 16;

    auto issue_kv = [&](int t, int b) {
        const float* kp = g_qkv + (size_t)(t * 64 + crow) * QKV_N + h * 64 + CDIM + cq16;
        uint32_t kd = smem_base + KV_OFF + b * KVSTRIDE + (crow * 68 + cq16) * 4;
        uint32_t vd = smem_base + KV_OFF + b * KVSTRIDE + V_SUB + (crow * 68 + cq16) * 4;
#pragma unroll
        for (int i = 0; i < 4; i++) {
            cp16(kd + i * 16, kp + i * 4);
            cp16(vd + i * 16, kp + CDIM + i * 4);
        }
        CP_COMMIT();
    };

    issue_kv(kt0, 0);

    const float* rh_base = g_relh + (size_t)h * 64 * S_TOK + q0 + w * 16 + rq;

    for (int kt = kt0; kt < kt1; kt++) {
        const int buf = (kt - kt0) & 1;
        __syncthreads();
        if (kt + 1 < kt1) issue_kv(kt + 1, buf ^ 1);
        float rhl = __ldg(rh_base + (size_t)kt * S_TOK);
        float rhh = __ldg(rh_base + (size_t)kt * S_TOK + 8);
        if (kt + 1 < kt1) { CP_WAIT1(); } else { CP_WAIT0(); }
        __syncthreads();

        const uint32_t* kp = (const uint32_t*)(smc + KV_OFF + buf * KVSTRIDE)
                           + (lane >> 2) * 68 + (lane & 3);
        const uint32_t* vp = (const uint32_t*)(smc + KV_OFF + buf * KVSTRIDE + V_SUB)
                           + 2 * (lane & 3) * 68 + (lane >> 2);

        // ---- S = Q @ K^T (logits already in log2 domain) ----
        float Sa[8][4];
#pragma unroll
        for (int nt = 0; nt < 8; nt++)
#pragma unroll
            for (int j = 0; j < 4; j++) Sa[nt][j] = 0.f;

#pragma unroll
        for (int ks = 0; ks < 8; ks++) {
#pragma unroll
            for (int nt = 0; nt < 8; nt++) {
                uint2 b = {kp[nt * 8 * 68 + ks * 8], kp[nt * 8 * 68 + ks * 8 + 4]};
                mma_tf32(Sa[nt], Qa[ks], b);
            }
        }

        // ---- bias + online softmax in base-2 (P left in Sa) ----
        float mlo = -1e30f, mhi = -1e30f;
#pragma unroll
        for (int nt = 0; nt < 8; nt++) {
            float4 rw = *(float4*)(sRWf + ((w * 8 + nt) * 32 + lane) * 4);
            Sa[nt][0] += rhl + rw.x;
            Sa[nt][1] += rhl + rw.y;
            Sa[nt][2] += rhh + rw.z;
            Sa[nt][3] += rhh + rw.w;
            mlo = fmaxf(mlo, fmaxf(Sa[nt][0], Sa[nt][1]));
            mhi = fmaxf(mhi, fmaxf(Sa[nt][2], Sa[nt][3]));
        }
        mlo = fmaxf(mlo, __shfl_xor_sync(0xffffffffu, mlo, 1));
        mlo = fmaxf(mlo, __shfl_xor_sync(0xffffffffu, mlo, 2));
        mhi = fmaxf(mhi, __shfl_xor_sync(0xffffffffu, mhi, 1));
        mhi = fmaxf(mhi, __shfl_xor_sync(0xffffffffu, mhi, 2));
        float mnl = fmaxf(m_lo, mlo);
        float mnh = fmaxf(m_hi, mhi);
        float al  = ex2(m_lo - mnl);
        float ah  = ex2(m_hi - mnh);
        m_lo = mnl; m_hi = mnh;

        float rsl = 0.f, rsh = 0.f;
#pragma unroll
        for (int nt = 0; nt < 8; nt++) {
            float p0 = ex2(Sa[nt][0] - mnl);
            float p1 = ex2(Sa[nt][1] - mnl);
            float p2 = ex2(Sa[nt][2] - mnh);
            float p3 = ex2(Sa[nt][3] - mnh);
            rsl += p0 + p1;
            rsh += p2 + p3;
            Sa[nt][0] = p0; Sa[nt][1] = p1; Sa[nt][2] = p2; Sa[nt][3] = p3;
        }
        rsl += __shfl_xor_sync(0xffffffffu, rsl, 1);
        rsl += __shfl_xor_sync(0xffffffffu, rsl, 2);
        rsh += __shfl_xor_sync(0xffffffffu, rsh, 1);
        rsh += __shfl_xor_sync(0xffffffffu, rsh, 2);
        l_lo = l_lo * al + rsl;
        l_hi = l_hi * ah + rsh;

#pragma unroll
        for (int nt = 0; nt < 8; nt++) {
            Oa[nt][0] *= al;
            Oa[nt][1] *= al;
            Oa[nt][2] *= ah;
            Oa[nt][3] *= ah;
        }

        // ---- O += P @ V : P A-frag = permuted C-frag, all in registers ----
#pragma unroll
        for (int ks = 0; ks < 8; ks++) {
            uint4 Pf = {f2tf32(Sa[ks][0]), f2tf32(Sa[ks][2]),
                        f2tf32(Sa[ks][1]), f2tf32(Sa[ks][3])};
            const uint32_t* vk = vp + ks * 8 * 68;
#pragma unroll
            for (int nt = 0; nt < 8; nt++) {
                uint2 b = {vk[nt * 8], vk[68 + nt * 8]};
                mma_tf32(Oa[nt], Pf, b);
            }
        }
    }

    // ---- epilogue: write UNNORMALIZED partial O + (m,l) (m in log2) ----
    float* part = g_part + ((size_t)sp * NH + h) * S_TOK * 64;
#pragma unroll
    for (int nt = 0; nt < 8; nt++) {
        int col = nt * 8 + 2 * (lane & 3);
        float2 v0 = {Oa[nt][0], Oa[nt][1]};
        float2 v1 = {Oa[nt][2], Oa[nt][3]};
        *(float2*)(part + (size_t)r0 * 64 + col)       = v0;
        *(float2*)(part + (size_t)(r0 + 8) * 64 + col) = v1;
    }
    if ((lane & 3) == 0) {
        float* ml = g_pml + ((size_t)sp * NH + h) * S_TOK * 2;
        ml[(size_t)r0 * 2]           = m_lo;
        ml[(size_t)r0 * 2 + 1]       = l_lo;
        ml[(size_t)(r0 + 8) * 2]     = m_hi;
        ml[(size_t)(r0 + 8) * 2 + 1] = l_hi;
    }
}

// ---------------------------------------------------------------------------
// Split-KV merge (base-2 weights): one warp per (h, q) row.
// ---------------------------------------------------------------------------
__global__ __launch_bounds__(256) void flash_merge_kernel(float* __restrict__ out)
{
    const int row  = blockIdx.x * 8 + (threadIdx.x >> 5);   // 0..NH*S_TOK-1
    const int lane = threadIdx.x & 31;
    const int h = row >> 12;
    const int q = row & (S_TOK - 1);

    const size_t mlstr = (size_t)NH * S_TOK * 2;
    float m0 = g_pml[(size_t)row * 2],               l0 = g_pml[(size_t)row * 2 + 1];
    float m1 = g_pml[mlstr + (size_t)row * 2],       l1 = g_pml[mlstr + (size_t)row * 2 + 1];
    float m2 = g_pml[2 * mlstr + (size_t)row * 2],   l2 = g_pml[2 * mlstr + (size_t)row * 2 + 1];
    float M  = fmaxf(fmaxf(m0, m1), m2);
    float w0 = ex2(m0 - M), w1 = ex2(m1 - M), w2 = ex2(m2 - M);
    float inv = 1.f / (l0 * w0 + l1 * w1 + l2 * w2);

    const size_t pstr = (size_t)NH * S_TOK * 64;
    const float* p0 = g_part + (size_t)row * 64;
    const float* p1 = p0 + pstr;
    const float* p2 = p1 + pstr;
    float* orow = out + (size_t)q * CDIM + h * 64;
#pragma unroll
    for (int c = 0; c < 2; c++) {
        int d = lane + 32 * c;
        float v = p0[d] * w0 + p1[d] * w1 + p2[d] * w2;
        orow[d] = __uint_as_float(f2tf32(v * inv));
    }
}

// ---------------------------------------------------------------------------
// Launch
// ---------------------------------------------------------------------------
extern "C" void kernel_launch(void* const* d_in, const int* in_sizes, int n_in,
                              void* d_out, int out_size)
{
    const float* x      = (const float*)d_in[0];
    const float* qkv_w  = (const float*)d_in[1];
    const float* qkv_b  = (const float*)d_in[2];
    const float* rph    = (const float*)d_in[3];
    const float* rpw    = (const float*)d_in[4];
    const float* proj_w = (const float*)d_in[5];
    const float* proj_b = (const float*)d_in[6];
    float* out = (float*)d_out;

    float *qkv, *attno, *xr, *wr;
    cudaGetSymbolAddress((void**)&qkv,   g_qkv);
    cudaGetSymbolAddress((void**)&attno, g_attno);
    cudaGetSymbolAddress((void**)&xr,    g_xr);
    cudaGetSymbolAddress((void**)&wr,    g_wr);

    cudaFuncSetAttribute(flash_mma_kernel,
                         cudaFuncAttributeMaxDynamicSharedMemorySize,
                         FLASH_SMEM);

    const int RB = 256;
    // 0. pre-round both GEMM inputs to tf32 in ONE launch
    {
        int n4x = (S_TOK * CDIM) / 4;
        int n4w = (CDIM * QKV_N) / 4;
        int tot = n4x + n4w;
        tf32_round2_kernel<<<(tot + RB - 1) / RB, RB>>>(x, xr, n4x, qkv_w, wr, n4w);
    }
    // 1. qkv = xr @ wr + qkv_b, output rounded to tf32
    {
        dim3 grid(QKV_N / 128, S_TOK / 128);
        gemm_tf32_kernel<<<grid, 256>>>(xr, wr, qkv_b, qkv,
                                        S_TOK, QKV_N, CDIM, 1);
    }
    // 2. rel-pos tables (x log2e), both modes in one launch
    {
        dim3 grid(64, NH, 2);
        relpos_kernel<<<grid, 256>>>(rph, rpw);
    }
    // 3. flash attention, 3-way split-KV (base-2 softmax)
    {
        dim3 grid(S_TOK / 128, NH, NSPLIT);
        flash_mma_kernel<<<grid, 256, FLASH_SMEM>>>();
    }
    // 3b. merge splits -> attno (tf32-rounded)
    {
        flash_merge_kernel<<<(NH * S_TOK) / 8, 256>>>(attno);
    }
    // 4. round proj weights, then proj GEMM
    {
        int n4 = (CDIM * CDIM) / 4;
        tf32_round_kernel<<<(n4 + RB - 1) / RB, RB>>>(proj_w, wr, n4);
        dim3 grid(CDIM / 128, S_TOK / 128);
        gemm_tf32_kernel<<<grid, 256>>>(attno, wr, proj_b, out,
                                        S_TOK, CDIM, CDIM, 0);
    }
}